// round 15
// baseline (speedup 1.0000x reference)
#include <cuda_runtime.h>
#include <math.h>

#define FRAME_SIZE 160
#define LPC_N 16
#define T_LEN 2400
#define T4 (T_LEN / 4)                 // 600 float4 per row
#define N_FRAMES 15
#define B_SZ 1024

#define FPB 3                          // frames per chunk
#define CHUNK (FRAME_SIZE * FPB)       // 480 samples
#define CHUNK4 (CHUNK / 4)             // 120 float4
#define NCHUNK (N_FRAMES / FPB)        // 5 chunks per row
#define NTHREADS 128
#define NWORK CHUNK4                   // 120 work threads

#define SCALE    (255.0f / 32768.0f)
#define SCALE_1  (32768.0f / 255.0f)

__device__ __forceinline__ float ex2_approx(float x) {
    float y; asm("ex2.approx.f32 %0, %1;" : "=f"(y) : "f"(x)); return y;
}
__device__ __forceinline__ float lg2_approx(float x) {
    float y; asm("lg2.approx.f32 %0, %1;" : "=f"(y) : "f"(x)); return y;
}

// mu-law decode, folded: w = v/16 - 8 => linear = copysign(SCALE_1*(2^|w|-1), w)
__device__ __forceinline__ float u2l(float v) {
    float w = fmaf(v, 0.0625f, -8.0f);
    float m = fmaf(SCALE_1, ex2_approx(fabsf(w)), -SCALE_1);
    return copysignf(m, w);
}
// l2u(-a) = clip(128 - copysign(16*log2(1 + SCALE*|a|), a), 0, 255)
__device__ __forceinline__ float l2u_neg(float a) {
    float u = lg2_approx(fmaf(SCALE, fabsf(a), 1.0f));
    float s = copysignf(16.0f, a);
    return fminf(fmaxf(fmaf(-s, u, 128.0f), 0.0f), 255.0f);
}

__device__ __forceinline__ float4 dec4(float4 v) {
    float4 d;
    d.x = u2l(v.x); d.y = u2l(v.y); d.z = u2l(v.z); d.w = u2l(v.w);
    return d;
}

// Persistent single-wave kernel: one block per batch row (1024 blocks ~= one
// wave on 148 SMs). Each block walks its row's 5 chunks with:
//   - software pipelining: next chunk's sig LDG issued before this chunk's FIR
//   - double-buffered smem + halo reuse: chunk k's halo = last 4 decoded
//     groups of chunk k-1, copied from the other buffer (no LDG, no decode)
// Per-chunk body identical to the R8/R14 champion (4 samples/thread).
__global__ __launch_bounds__(NTHREADS)
void diff_pred_kernel(const float4* __restrict__ sig,
                      const float*  __restrict__ lpc,
                      float4* __restrict__ out) {
    __shared__ __align__(16) float4 sbuf[2][4 + CHUNK4];   // double buffer

    const int b   = blockIdx.x;
    const int tid = threadIdx.x;
    const float4* srow = sig + (size_t)b * T4;
    const float*  lrow_base = lpc + (size_t)b * (N_FRAMES * LPC_N);
    float4* orow = out + (size_t)b * T4;

    const bool work = (tid < NWORK);
    const int  fl   = tid / (FRAME_SIZE / 4);   // frame-within-chunk: 0..2

    // ---- prologue: load chunk 0 ----
    float4 vcur;
    if (work) vcur = srow[tid];

    int p = 0;
#pragma unroll 1
    for (int ck = 0; ck < NCHUNK; ++ck) {
        const int base4 = ck * CHUNK4;

        // -- pipeline: issue next chunk's load before any compute --
        float4 vnext;
        if (ck + 1 < NCHUNK && work) vnext = srow[base4 + CHUNK4 + tid];

        // -- coefficients for this thread's frame (L1-hot after first iter) --
        float4 c0, c1, c2, c3;
        if (work) {
            const float4* lrow = (const float4*)(lrow_base
                                 + (ck * FPB + fl) * LPC_N);
            c0 = lrow[0]; c1 = lrow[1]; c2 = lrow[2]; c3 = lrow[3];
        }

        // -- decode + stage --
        float4 d;
        if (work) {
            d = dec4(vcur);
            sbuf[p][4 + tid] = d;
        } else if (tid < NWORK + 4) {
            const int k = tid - NWORK;           // 0..3
            // halo = last 4 decoded groups of previous chunk (other buffer);
            // chunk 0: zero history
            sbuf[p][k] = (ck == 0) ? make_float4(0.f, 0.f, 0.f, 0.f)
                                   : sbuf[p ^ 1][4 + CHUNK4 - 4 + k];
        }
        __syncthreads();

        if (work) {
            // window x[0..15] from shared; x[16..19] = own decode (regs)
            float x[20];
#pragma unroll
            for (int k = 0; k < 4; ++k) {
                float4 xx = sbuf[p][tid + k];
                x[4 * k] = xx.x; x[4 * k + 1] = xx.y;
                x[4 * k + 2] = xx.z; x[4 * k + 3] = xx.w;
            }
            x[16] = d.x; x[17] = d.y; x[18] = d.z; x[19] = d.w;

            const float c[LPC_N] = { c0.x, c0.y, c0.z, c0.w,
                                     c1.x, c1.y, c1.z, c1.w,
                                     c2.x, c2.y, c2.z, c2.w,
                                     c3.x, c3.y, c3.z, c3.w };

            float a0 = 0.f, a1 = 0.f, a2 = 0.f, a3 = 0.f;
#pragma unroll
            for (int i = 0; i < LPC_N; ++i) {
                a0 = fmaf(c[i], x[16 - i], a0);
                a1 = fmaf(c[i], x[17 - i], a1);
                a2 = fmaf(c[i], x[18 - i], a2);
                a3 = fmaf(c[i], x[19 - i], a3);
            }

            float4 r;
            r.x = l2u_neg(a0); r.y = l2u_neg(a1);
            r.z = l2u_neg(a2); r.w = l2u_neg(a3);
            orow[base4 + tid] = r;
        }

        vcur = vnext;
        p ^= 1;
    }
}

extern "C" void kernel_launch(void* const* d_in, const int* in_sizes, int n_in,
                              void* d_out, int out_size) {
    const float4* sig = (const float4*)d_in[0];  // (B, 2400, 1) f32
    const float*  lpc = (const float*)d_in[1];   // (B, 15, 16) f32
    float4* out = (float4*)d_out;                // (B, 2400, 1) f32

    diff_pred_kernel<<<B_SZ, NTHREADS>>>(sig, lpc, out);
}

// round 16
// speedup vs baseline: 1.0060x; 1.0060x over previous
#include <cuda_runtime.h>
#include <math.h>

#define FRAME_SIZE 160
#define LPC_N 16
#define T_LEN 2400
#define T4 (T_LEN / 4)               // 600 float4 groups per row
#define N_FRAMES 15
#define B_SZ 1024

#define OG 60                        // output groups per warp (240 samples)
#define WARPS_PER_ROW (T4 / OG)      // 10
#define WPB 4
#define NTHREADS (WPB * 32)
#define NBLOCKS (B_SZ * WARPS_PER_ROW / WPB)   // 2560

#define SCALE    (255.0f / 32768.0f)
#define SCALE_1  (32768.0f / 255.0f)

__device__ __forceinline__ float ex2_approx(float x) {
    float y; asm("ex2.approx.f32 %0, %1;" : "=f"(y) : "f"(x)); return y;
}
__device__ __forceinline__ float lg2_approx(float x) {
    float y; asm("lg2.approx.f32 %0, %1;" : "=f"(y) : "f"(x)); return y;
}

// mu-law decode, folded: w = v/16 - 8 => linear = copysign(SCALE_1*(2^|w|-1), w)
// u2l(128) == +0 exactly (history pad).
__device__ __forceinline__ float u2l(float v) {
    float w = fmaf(v, 0.0625f, -8.0f);
    float m = fmaf(SCALE_1, ex2_approx(fabsf(w)), -SCALE_1);
    return copysignf(m, w);
}
// l2u(-a) = clip(128 - copysign(16*log2(1 + SCALE*|a|), a), 0, 255)
__device__ __forceinline__ float l2u_neg(float a) {
    float u = lg2_approx(fmaf(SCALE, fabsf(a), 1.0f));
    float s = copysignf(16.0f, a);
    return fminf(fmaxf(fmaf(-s, u, 128.0f), 0.0f), 255.0f);
}

__device__ __forceinline__ float4 dec4(float4 v) {
    float4 d;
    d.x = u2l(v.x); d.y = u2l(v.y); d.z = u2l(v.z); d.w = u2l(v.w);
    return d;
}

// Warp-autonomous, zero-waste tile, sequential two-pass FIR:
//   warp w: row b = w/10, segment r = w%10. Owns output groups [60r, 60r+60).
//   Every lane decodes EXACTLY 2 consecutive groups (64 groups = 60 output
//   + 4 halo) in one uniform pass — no predicated second decode, no remap.
//   Lanes 0..29 then produce 2 output groups SEQUENTIALLY, sliding a
//   20-float window (register shift + 1 LDS.128) so the live set stays
//   R8-sized. __syncwarp only — no block barrier.
__global__ __launch_bounds__(NTHREADS)
void diff_pred_kernel(const float4* __restrict__ sig,
                      const float*  __restrict__ lpc,
                      float4* __restrict__ out) {
    __shared__ __align__(16) float4 strip[WPB][OG + 4];   // 64 slots per warp

    const int wid = threadIdx.x >> 5;
    const int l   = threadIdx.x & 31;
    const int w   = blockIdx.x * WPB + wid;
    const int b   = w / WARPS_PER_ROW;
    const int r   = w - b * WARPS_PER_ROW;
    const int gb  = OG * r;                   // row-local output group base
    const int q0  = gb - 4 + 2 * l;           // this lane's first decode group

    const float4* srow = sig + (size_t)b * T4;

    // ---- front-batch all global loads ----
    const float4 pad = make_float4(128.f, 128.f, 128.f, 128.f);  // decodes to 0
    float4 v0 = (q0 >= 0)     ? srow[q0]     : pad;
    float4 v1 = (q0 + 1 >= 0) ? srow[q0 + 1] : pad;

    // coefficients for this lane's output pair (both groups in one frame:
    // g0 = gb + 2l is even, frame boundary at multiples of 40)
    float4 c0, c1, c2, c3;
    if (l < OG / 2) {
        const int g0 = gb + 2 * l;
        const int f  = g0 / (FRAME_SIZE / 4);            // g0 / 40
        const float4* lrow = (const float4*)(lpc + (size_t)b * (N_FRAMES * LPC_N)
                                             + f * LPC_N);
        c0 = lrow[0]; c1 = lrow[1]; c2 = lrow[2]; c3 = lrow[3];
    }

    // ---- single uniform decode pass (2 groups per lane) ----
    strip[wid][2 * l]     = dec4(v0);
    strip[wid][2 * l + 1] = dec4(v1);
    __syncwarp();

    if (l >= OG / 2) return;

    const float c[LPC_N] = { c0.x, c0.y, c0.z, c0.w, c1.x, c1.y, c1.z, c1.w,
                             c2.x, c2.y, c2.z, c2.w, c3.x, c3.y, c3.z, c3.w };

    float4* orow = out + (size_t)b * T4;
    const int og = gb + 2 * l;

    // ---- pass A: output group og, window = strip slots 2l .. 2l+4 ----
    float x[20];
#pragma unroll
    for (int k = 0; k < 5; ++k) {
        float4 xx = strip[wid][2 * l + k];
        x[4 * k] = xx.x; x[4 * k + 1] = xx.y; x[4 * k + 2] = xx.z; x[4 * k + 3] = xx.w;
    }
    {
        float a0 = 0.f, a1 = 0.f, a2 = 0.f, a3 = 0.f;
#pragma unroll
        for (int i = 0; i < LPC_N; ++i) {
            a0 = fmaf(c[i], x[16 - i], a0);
            a1 = fmaf(c[i], x[17 - i], a1);
            a2 = fmaf(c[i], x[18 - i], a2);
            a3 = fmaf(c[i], x[19 - i], a3);
        }
        float4 rA;
        rA.x = l2u_neg(a0); rA.y = l2u_neg(a1); rA.z = l2u_neg(a2); rA.w = l2u_neg(a3);
        orow[og] = rA;
    }

    // ---- pass B: slide window by one group (register shift + 1 LDS.128) ----
#pragma unroll
    for (int i = 0; i < 16; ++i) x[i] = x[i + 4];
    {
        float4 xx = strip[wid][2 * l + 5];
        x[16] = xx.x; x[17] = xx.y; x[18] = xx.z; x[19] = xx.w;

        float a0 = 0.f, a1 = 0.f, a2 = 0.f, a3 = 0.f;
#pragma unroll
        for (int i = 0; i < LPC_N; ++i) {
            a0 = fmaf(c[i], x[16 - i], a0);
            a1 = fmaf(c[i], x[17 - i], a1);
            a2 = fmaf(c[i], x[18 - i], a2);
            a3 = fmaf(c[i], x[19 - i], a3);
        }
        float4 rB;
        rB.x = l2u_neg(a0); rB.y = l2u_neg(a1); rB.z = l2u_neg(a2); rB.w = l2u_neg(a3);
        orow[og + 1] = rB;
    }
}

extern "C" void kernel_launch(void* const* d_in, const int* in_sizes, int n_in,
                              void* d_out, int out_size) {
    const float4* sig = (const float4*)d_in[0];  // (B, 2400, 1) f32
    const float*  lpc = (const float*)d_in[1];   // (B, 15, 16) f32
    float4* out = (float4*)d_out;                // (B, 2400, 1) f32

    diff_pred_kernel<<<NBLOCKS, NTHREADS>>>(sig, lpc, out);
}